// round 16
// baseline (speedup 1.0000x reference)
#include <cuda_runtime.h>
#include <cuda_fp16.h>
#include <stdint.h>

#define NS 32
#define TT 2048
#define ND 1024
#define GRID 128
#define NTHREADS 256
#define NWARPS 8
#define KTILES 8     // 8 warps * 8 ktiles * 16 = 1024 = K
#define ROWBLK 32    // A rows per CTA
#define SBLK 8       // samples per CTA
#define SGROUPS 4
#define NCH ((TT - 2) / 2)   // 1023 double-step chunks

#define ALPHA 0.1f
#define BETA  0.9f
#define A2C   (ALPHA * ALPHA)
#define ABC   (ALPHA * BETA)

// Double-buffered fp16 hidden state, pre-swizzled mma-B layout.
__device__ __align__(16) __half g_hbuf[2][NS * ND];
// A@A (row-major fp32), computed once per launch in phase 1.
__device__ float g_A2[ND * ND];
// Producer flags: g_flags[sb][rb] = completed productions by CTA (rb, sb).
__device__ __align__(256) volatile unsigned g_flags[SGROUPS][32];
// Sense-reversing grid barrier (phase transitions + cleanup only).
__device__ unsigned g_bar_count;
__device__ unsigned g_bar_gen;

__device__ __forceinline__ void grid_barrier() {
    __syncthreads();
    if (threadIdx.x == 0) {
        unsigned gen = *((volatile unsigned*)&g_bar_gen);
        __threadfence();
        unsigned old = atomicAdd(&g_bar_count, 1u);
        if (old == GRID - 1) {
            g_bar_count = 0;
            __threadfence();
            atomicExch(&g_bar_gen, gen + 1u);
        } else {
            while (*((volatile unsigned*)&g_bar_gen) == gen) { }
        }
        __threadfence();
    }
    __syncthreads();
}

__device__ __forceinline__ void mma16816(float* d, const uint32_t* a,
                                         uint32_t b0, uint32_t b1) {
    asm volatile(
        "mma.sync.aligned.m16n8k16.row.col.f32.f16.f16.f32 "
        "{%0,%1,%2,%3}, {%4,%5,%6,%7}, {%8,%9}, {%0,%1,%2,%3};\n"
        : "+f"(d[0]), "+f"(d[1]), "+f"(d[2]), "+f"(d[3])
        : "r"(a[0]), "r"(a[1]), "r"(a[2]), "r"(a[3]), "r"(b0), "r"(b1));
}

// Swizzled position of logical element j (per 16-block order 0,1,8,9,2,3,...).
__device__ __forceinline__ int hpos(int j) {
    int r = j & 15;
    return (j & ~15) + ((r & 6) << 1) + ((r >> 3) << 1) + (r & 1);
}

__device__ __forceinline__ unsigned flag_acquire(const volatile unsigned* p) {
    unsigned v;
    asm volatile("ld.global.acquire.gpu.u32 %0, [%1];"
                 : "=r"(v) : "l"((const unsigned*)p) : "memory");
    return v;
}

__device__ __forceinline__ void flag_release(volatile unsigned* p, unsigned v) {
    asm volatile("st.global.release.gpu.u32 [%0], %1;"
                 :: "l"((unsigned*)p), "r"(v) : "memory");
}

__device__ __forceinline__ void prefetch_l2(const void* p) {
    asm volatile("prefetch.global.L2 [%0];" :: "l"(p));
}

__device__ __forceinline__ void load_afrag(uint32_t* f, const float* src,
                                           int row, int k0) {
    const float* p = src + (size_t)row * ND + k0;
    float2 v0 = *(const float2*)(p);
    float2 v1 = *(const float2*)(p + 8 * (size_t)ND);
    float2 v2 = *(const float2*)(p + 8);
    float2 v3 = *(const float2*)(p + 8 * (size_t)ND + 8);
    __half2 q0 = __floats2half2_rn(v0.x, v0.y);
    __half2 q1 = __floats2half2_rn(v1.x, v1.y);
    __half2 q2 = __floats2half2_rn(v2.x, v2.y);
    __half2 q3 = __floats2half2_rn(v3.x, v3.y);
    f[0] = *(uint32_t*)&q0; f[1] = *(uint32_t*)&q1;
    f[2] = *(uint32_t*)&q2; f[3] = *(uint32_t*)&q3;
}

__global__ __launch_bounds__(NTHREADS, 1) void rnn_kernel(
    const float* __restrict__ inp,   // [NS, TT, ND]
    const float* __restrict__ A,     // [ND, ND]
    const float* __restrict__ h0,    // [NS, ND]
    float* __restrict__ out)         // [NS, TT, ND]
{
    // Interleaved psum: .x = P1 partials, .y = D2 partials. 16 KB.
    __shared__ float2 psum[NWARPS][SBLK * ROWBLK];

    const int tid  = threadIdx.x;
    const int w    = tid >> 5;
    const int lane = tid & 31;
    const int g    = lane >> 2;
    const int tig  = lane & 3;

    const int cta  = blockIdx.x;
    const int rb   = cta >> 2;        // 32 row blocks
    const int sb   = cta & 3;         // 4 sample groups
    const int row0 = rb * ROWBLK;
    const int s0   = sb * SBLK;

    // ---- Resident A fragments (k-split across warps) ----
    uint32_t afrag[KTILES][2][4];
#pragma unroll
    for (int kt = 0; kt < KTILES; kt++) {
        int k0 = (w * KTILES + kt) * 16 + 2 * tig;
        load_afrag(afrag[kt][0], A, row0 + g, k0);
        load_afrag(afrag[kt][1], A, row0 + 16 + g, k0);
    }

    // ========== Phase 1: A2 = A @ A, all 128 CTAs, j-split by sb ==========
    for (int jj = 0; jj < 32; jj++) {
        const int jblk = sb * 32 + jj;
        const int j    = jblk * 8 + g;
        float d[2][4];
#pragma unroll
        for (int m = 0; m < 2; m++)
#pragma unroll
            for (int c = 0; c < 4; c++) d[m][c] = 0.0f;

#pragma unroll
        for (int kt = 0; kt < KTILES; kt++) {
            const int kb = (w * KTILES + kt) * 16;
            float e0 = A[(size_t)(kb + 2 * tig)     * ND + j];
            float e1 = A[(size_t)(kb + 2 * tig + 1) * ND + j];
            float e2 = A[(size_t)(kb + 2 * tig + 8) * ND + j];
            float e3 = A[(size_t)(kb + 2 * tig + 9) * ND + j];
            __half2 hb0 = __floats2half2_rn(e0, e1);
            __half2 hb1 = __floats2half2_rn(e2, e3);
            uint32_t b0 = *(uint32_t*)&hb0;
            uint32_t b1 = *(uint32_t*)&hb1;
            mma16816(d[0], afrag[kt][0], b0, b1);
            mma16816(d[1], afrag[kt][1], b0, b1);
        }
#pragma unroll
        for (int m = 0; m < 2; m++)
#pragma unroll
            for (int c = 0; c < 4; c++) {
                int i_loc = m * 16 + g + ((c >> 1) << 3);
                int j_loc = tig * 2 + (c & 1);
                psum[w][j_loc * ROWBLK + i_loc].x = d[m][c];
            }
        __syncthreads();
        {
            int i_loc = tid & 31;
            int j_loc = tid >> 5;
            float s = 0.f;
#pragma unroll
            for (int ww = 0; ww < NWARPS; ww++)
                s += psum[ww][j_loc * ROWBLK + i_loc].x;
            g_A2[(size_t)(row0 + i_loc) * ND + jblk * 8 + j_loc] = s;
        }
        __syncthreads();
    }
    grid_barrier();

    // ---- Resident A^2 fragments ----
    uint32_t a2frag[KTILES][2][4];
#pragma unroll
    for (int kt = 0; kt < KTILES; kt++) {
        int k0 = (w * KTILES + kt) * 16 + 2 * tig;
        load_afrag(a2frag[kt][0], g_A2, row0 + g, k0);
        load_afrag(a2frag[kt][1], g_A2, row0 + 16 + g, k0);
    }

    // ---- Per-thread state ownership: 1 element each ----
    const int s_l  = tid >> 5;            // 0..7
    const int i_l  = tid & 31;            // 0..31
    const int s_gl = s0 + s_l;
    const int i_gl = row0 + i_l;
    const int e    = s_l * ROWBLK + i_l;

    const float* inp_base = inp + (size_t)s_gl * TT * ND + i_gl;
    float* out_base       = out + (size_t)s_gl * TT * ND + i_gl;
    const int hslot = s_gl * ND + hpos(i_gl);

    // Dedup prefetch: thread (tid&31)==rb covers line rb of 8 sample rows.
    const bool do_pf = ((tid & 31) == rb);
    const float* pf_base = inp + (size_t)(s0 + (tid >> 5)) * TT * ND + rb * 32;

    // ---- Production 0: h0 ----
    float hprev = h0[(size_t)s_gl * ND + i_gl];
    out_base[0] = hprev;
    g_hbuf[0][hslot] = __float2half_rn(hprev);
    __syncthreads();
    if (tid == 0) flag_release(&g_flags[sb][rb], 1u);

    // Warm prefetch for rows 0..3 (chunk 0 xa/xb + pipelined Q(1) row 2).
    if (do_pf) {
        prefetch_l2(pf_base);
        prefetch_l2(pf_base + ND);
        prefetch_l2(pf_base + 2 * (size_t)ND);
        prefetch_l2(pf_base + 3 * (size_t)ND);
    }

    // x base for the Q GEMM (B operand rows = samples s0+g).
    const float* xq_base = inp + (size_t)(s0 + g) * TT * ND;

    // ---- Prologue: Q(0) = A x_0 into the carried accumulator qn ----
    float qn[2][4];
#pragma unroll
    for (int m = 0; m < 2; m++)
#pragma unroll
        for (int c = 0; c < 4; c++) qn[m][c] = 0.f;
#pragma unroll
    for (int kt = 0; kt < KTILES; kt++) {
        int kb = (w * KTILES + kt) * 16 + 2 * tig;
        const float* xp = xq_base + kb;     // row 0
        float2 v0 = __ldcs((const float2*)xp);
        float2 v1 = __ldcs((const float2*)(xp + 8));
        __half2 hq0 = __floats2half2_rn(v0.x, v0.y);
        __half2 hq1 = __floats2half2_rn(v1.x, v1.y);
        mma16816(qn[0], afrag[kt][0], *(uint32_t*)&hq0, *(uint32_t*)&hq1);
        mma16816(qn[1], afrag[kt][1], *(uint32_t*)&hq0, *(uint32_t*)&hq1);
    }

    // ================= Main loop: 1023 double-steps, Q pipelined =================
    for (int s = 0; s < NCH; s++) {
        const int ts = 2 * s;   // produces h[ts+1], h[ts+2] from h[ts]

        float xa = __ldcs(inp_base + (size_t)ts * ND);
        float xb = __ldcs(inp_base + (size_t)(ts + 1) * ND);

        // d1: A h (single chain); d2a inherits carried Q(s); d2b: split partner.
        float d1[2][4], d2a[2][4], d2b[2][4];
#pragma unroll
        for (int m = 0; m < 2; m++)
#pragma unroll
            for (int c = 0; c < 4; c++) {
                d1[m][c]  = 0.f;
                d2a[m][c] = qn[m][c];
                d2b[m][c] = 0.f;
                qn[m][c]  = 0.f;
            }

        // Prefetch rows ts+4, ts+5 (consumed by chunk s+1's xa/xb and s+2's Q).
        if (do_pf && ts + 4 < TT) {
            prefetch_l2(pf_base + (size_t)(ts + 4) * ND);
            prefetch_l2(pf_base + (size_t)(ts + 5) * ND);
        }

        // ---- Wait: warp 0 polls all 32 producers of this group ----
        if (w == 0) {
            const volatile unsigned* f = &g_flags[sb][lane];
            unsigned v = flag_acquire(f);
            while (__ballot_sync(0xffffffffu, v < (unsigned)(s + 1))) {
                if (v < (unsigned)(s + 1)) v = flag_acquire(f);
            }
        }
        __syncthreads();

        const __half* hb = g_hbuf[s & 1];

        // ---- P1 = A h, D2 += A^2 h (split d2 chains) ----
#pragma unroll
        for (int kt = 0; kt < KTILES; kt++) {
            int koff = (w * KTILES + kt) * 16 + tig * 4;
            uint2 b = *(const uint2*)(hb + (size_t)(s0 + g) * ND + koff);
            float* t0 = (kt & 1) ? d2b[0] : d2a[0];
            float* t1 = (kt & 1) ? d2b[1] : d2a[1];
            mma16816(d1[0], afrag[kt][0],  b.x, b.y);
            mma16816(d1[1], afrag[kt][1],  b.x, b.y);
            mma16816(t0, a2frag[kt][0], b.x, b.y);
            mma16816(t1, a2frag[kt][1], b.x, b.y);
        }

        // ---- Pipelined Q(s+1) = A x_{ts+2}: independent of hb; ptxas
        // interleaves these loads/MMAs into the P-chain's latency gaps. ----
        if (s + 1 < NCH) {
#pragma unroll
            for (int kt = 0; kt < KTILES; kt++) {
                int kb = (w * KTILES + kt) * 16 + 2 * tig;
                const float* xp = xq_base + (size_t)(ts + 2) * ND + kb;
                float2 v0 = __ldcs((const float2*)xp);
                float2 v1 = __ldcs((const float2*)(xp + 8));
                __half2 hq0 = __floats2half2_rn(v0.x, v0.y);
                __half2 hq1 = __floats2half2_rn(v1.x, v1.y);
                mma16816(qn[0], afrag[kt][0], *(uint32_t*)&hq0, *(uint32_t*)&hq1);
                mma16816(qn[1], afrag[kt][1], *(uint32_t*)&hq0, *(uint32_t*)&hq1);
            }
        }

        // ---- cross-warp reduction (interleaved float2) ----
#pragma unroll
        for (int m = 0; m < 2; m++)
#pragma unroll
            for (int c = 0; c < 4; c++) {
                int i_loc = m * 16 + g + ((c >> 1) << 3);
                int s_loc = tig * 2 + (c & 1);
                psum[w][s_loc * ROWBLK + i_loc] =
                    make_float2(d1[m][c], d2a[m][c] + d2b[m][c]);
            }
        __syncthreads();

        float P1 = 0.f, D2 = 0.f;
#pragma unroll
        for (int ww = 0; ww < NWARPS; ww++) {
            float2 p = psum[ww][e];
            P1 += p.x; D2 += p.y;
        }

        float h1 = BETA * hprev + ALPHA * (P1 + xa);
        float h2 = BETA * h1 + ABC * P1 + A2C * D2 + ALPHA * xb;
        hprev = h2;

        // Publish state first (critical path), outputs after the release.
        g_hbuf[(s + 1) & 1][hslot] = __float2half_rn(h2);
        __syncthreads();
        if (tid == 0) flag_release(&g_flags[sb][rb], (unsigned)(s + 2));

        __stcs(out_base + (size_t)(ts + 1) * ND, h1);
        __stcs(out_base + (size_t)(ts + 2) * ND, h2);
    }

    // ================= Epilogue: final single step t = TT-1 =================
    {
        const int s  = NCH;            // 1023
        const int ts = 2 * s;          // 2046
        float xa = __ldcs(inp_base + (size_t)ts * ND);

        if (w == 0) {
            const volatile unsigned* f = &g_flags[sb][lane];
            unsigned v = flag_acquire(f);
            while (__ballot_sync(0xffffffffu, v < (unsigned)(s + 1))) {
                if (v < (unsigned)(s + 1)) v = flag_acquire(f);
            }
        }
        __syncthreads();

        const __half* hb = g_hbuf[s & 1];
        float d1[2][4];
#pragma unroll
        for (int m = 0; m < 2; m++)
#pragma unroll
            for (int c = 0; c < 4; c++) d1[m][c] = 0.f;

#pragma unroll
        for (int kt = 0; kt < KTILES; kt++) {
            int koff = (w * KTILES + kt) * 16 + tig * 4;
            uint2 b = *(const uint2*)(hb + (size_t)(s0 + g) * ND + koff);
            mma16816(d1[0], afrag[kt][0], b.x, b.y);
            mma16816(d1[1], afrag[kt][1], b.x, b.y);
        }
#pragma unroll
        for (int m = 0; m < 2; m++)
#pragma unroll
            for (int c = 0; c < 4; c++) {
                int i_loc = m * 16 + g + ((c >> 1) << 3);
                int s_loc = tig * 2 + (c & 1);
                psum[w][s_loc * ROWBLK + i_loc].x = d1[m][c];
            }
        __syncthreads();

        float P1 = 0.f;
#pragma unroll
        for (int ww = 0; ww < NWARPS; ww++) P1 += psum[ww][e].x;

        float h1 = BETA * hprev + ALPHA * (P1 + xa);
        __stcs(out_base + (size_t)(ts + 1) * ND, h1);
    }

    // ---- Cleanup so graph replays start from flags == 0 ----
    grid_barrier();
    if (tid == 0) g_flags[sb][rb] = 0u;
}

extern "C" void kernel_launch(void* const* d_in, const int* in_sizes, int n_in,
                              void* d_out, int out_size) {
    const float* inp = (const float*)d_in[0];
    const float* A   = (const float*)d_in[1];
    const float* h0  = (const float*)d_in[2];
    float* out       = (float*)d_out;
    rnn_kernel<<<GRID, NTHREADS>>>(inp, A, h0, out);
}

// round 17
// speedup vs baseline: 2.1143x; 2.1143x over previous
#include <cuda_runtime.h>
#include <cuda_fp16.h>
#include <stdint.h>

#define NS 32
#define TT 2048
#define ND 1024
#define GRID 128
#define NTHREADS 256
#define NWARPS 8
#define KTILES 8     // 8 warps * 8 ktiles * 16 = 1024 = K
#define ROWBLK 32    // A rows per CTA
#define SBLK 8       // samples per CTA
#define SGROUPS 4

#define ALPHA 0.1f
#define BETA  0.9f
#define A2C   (ALPHA * ALPHA)
#define ABC   (ALPHA * BETA)

// Double-buffered fp16 hidden state, pre-swizzled mma-B layout.
__device__ __align__(16) __half g_hbuf[2][NS * ND];
// A@A (row-major fp32), computed once per launch in phase 1.
__device__ float g_A2[ND * ND];
// Producer flags: g_flags[sb][rb] = completed productions by CTA (rb, sb).
__device__ __align__(256) volatile unsigned g_flags[SGROUPS][32];
// Sense-reversing grid barrier (phase transitions + cleanup only).
__device__ unsigned g_bar_count;
__device__ unsigned g_bar_gen;

__device__ __forceinline__ void grid_barrier() {
    __syncthreads();
    if (threadIdx.x == 0) {
        unsigned gen = *((volatile unsigned*)&g_bar_gen);
        __threadfence();
        unsigned old = atomicAdd(&g_bar_count, 1u);
        if (old == GRID - 1) {
            g_bar_count = 0;
            __threadfence();
            atomicExch(&g_bar_gen, gen + 1u);
        } else {
            while (*((volatile unsigned*)&g_bar_gen) == gen) { }
        }
        __threadfence();
    }
    __syncthreads();
}

__device__ __forceinline__ void mma16816(float* d, const uint32_t* a,
                                         uint32_t b0, uint32_t b1) {
    asm volatile(
        "mma.sync.aligned.m16n8k16.row.col.f32.f16.f16.f32 "
        "{%0,%1,%2,%3}, {%4,%5,%6,%7}, {%8,%9}, {%0,%1,%2,%3};\n"
        : "+f"(d[0]), "+f"(d[1]), "+f"(d[2]), "+f"(d[3])
        : "r"(a[0]), "r"(a[1]), "r"(a[2]), "r"(a[3]), "r"(b0), "r"(b1));
}

// Swizzled position of logical element j (per 16-block order 0,1,8,9,2,3,...).
__device__ __forceinline__ int hpos(int j) {
    int r = j & 15;
    return (j & ~15) + ((r & 6) << 1) + ((r >> 3) << 1) + (r & 1);
}

__device__ __forceinline__ unsigned flag_acquire(const volatile unsigned* p) {
    unsigned v;
    asm volatile("ld.global.acquire.gpu.u32 %0, [%1];"
                 : "=r"(v) : "l"((const unsigned*)p) : "memory");
    return v;
}

__device__ __forceinline__ void flag_release(volatile unsigned* p, unsigned v) {
    asm volatile("st.global.release.gpu.u32 [%0], %1;"
                 :: "l"((unsigned*)p), "r"(v) : "memory");
}

__device__ __forceinline__ void prefetch_l2(const void* p) {
    asm volatile("prefetch.global.L2 [%0];" :: "l"(p));
}

__device__ __forceinline__ void load_afrag(uint32_t* f, const float* src,
                                           int row, int k0) {
    const float* p = src + (size_t)row * ND + k0;
    float2 v0 = *(const float2*)(p);
    float2 v1 = *(const float2*)(p + 8 * (size_t)ND);
    float2 v2 = *(const float2*)(p + 8);
    float2 v3 = *(const float2*)(p + 8 * (size_t)ND + 8);
    __half2 q0 = __floats2half2_rn(v0.x, v0.y);
    __half2 q1 = __floats2half2_rn(v1.x, v1.y);
    __half2 q2 = __floats2half2_rn(v2.x, v2.y);
    __half2 q3 = __floats2half2_rn(v3.x, v3.y);
    f[0] = *(uint32_t*)&q0; f[1] = *(uint32_t*)&q1;
    f[2] = *(uint32_t*)&q2; f[3] = *(uint32_t*)&q3;
}

__global__ __launch_bounds__(NTHREADS, 1) void rnn_kernel(
    const float* __restrict__ inp,   // [NS, TT, ND]
    const float* __restrict__ A,     // [ND, ND]
    const float* __restrict__ h0,    // [NS, ND]
    float* __restrict__ out)         // [NS, TT, ND]
{
    // Interleaved psum: .x = P1 partials, .y = D2 partials. 16 KB.
    __shared__ float2 psum[NWARPS][SBLK * ROWBLK];

    const int tid  = threadIdx.x;
    const int w    = tid >> 5;
    const int lane = tid & 31;
    const int g    = lane >> 2;
    const int tig  = lane & 3;

    const int cta  = blockIdx.x;
    const int rb   = cta >> 2;        // 32 row blocks
    const int sb   = cta & 3;         // 4 sample groups
    const int row0 = rb * ROWBLK;
    const int s0   = sb * SBLK;

    // ---- Resident A fragments (k-split across warps) ----
    uint32_t afrag[KTILES][2][4];
#pragma unroll
    for (int kt = 0; kt < KTILES; kt++) {
        int k0 = (w * KTILES + kt) * 16 + 2 * tig;
        load_afrag(afrag[kt][0], A, row0 + g, k0);
        load_afrag(afrag[kt][1], A, row0 + 16 + g, k0);
    }

    // ========== Phase 1: A2 = A @ A, all 128 CTAs, j-split by sb ==========
    for (int jj = 0; jj < 32; jj++) {
        const int jblk = sb * 32 + jj;
        const int j    = jblk * 8 + g;
        float d[2][4];
#pragma unroll
        for (int m = 0; m < 2; m++)
#pragma unroll
            for (int c = 0; c < 4; c++) d[m][c] = 0.0f;

#pragma unroll
        for (int kt = 0; kt < KTILES; kt++) {
            const int kb = (w * KTILES + kt) * 16;
            float e0 = A[(size_t)(kb + 2 * tig)     * ND + j];
            float e1 = A[(size_t)(kb + 2 * tig + 1) * ND + j];
            float e2 = A[(size_t)(kb + 2 * tig + 8) * ND + j];
            float e3 = A[(size_t)(kb + 2 * tig + 9) * ND + j];
            __half2 hb0 = __floats2half2_rn(e0, e1);
            __half2 hb1 = __floats2half2_rn(e2, e3);
            uint32_t b0 = *(uint32_t*)&hb0;
            uint32_t b1 = *(uint32_t*)&hb1;
            mma16816(d[0], afrag[kt][0], b0, b1);
            mma16816(d[1], afrag[kt][1], b0, b1);
        }
#pragma unroll
        for (int m = 0; m < 2; m++)
#pragma unroll
            for (int c = 0; c < 4; c++) {
                int i_loc = m * 16 + g + ((c >> 1) << 3);
                int j_loc = tig * 2 + (c & 1);
                psum[w][j_loc * ROWBLK + i_loc].x = d[m][c];
            }
        __syncthreads();
        {
            int i_loc = tid & 31;
            int j_loc = tid >> 5;
            float s = 0.f;
#pragma unroll
            for (int ww = 0; ww < NWARPS; ww++)
                s += psum[ww][j_loc * ROWBLK + i_loc].x;
            g_A2[(size_t)(row0 + i_loc) * ND + jblk * 8 + j_loc] = s;
        }
        __syncthreads();
    }
    grid_barrier();

    // ---- Resident A^2 fragments ----
    uint32_t a2frag[KTILES][2][4];
#pragma unroll
    for (int kt = 0; kt < KTILES; kt++) {
        int k0 = (w * KTILES + kt) * 16 + 2 * tig;
        load_afrag(a2frag[kt][0], g_A2, row0 + g, k0);
        load_afrag(a2frag[kt][1], g_A2, row0 + 16 + g, k0);
    }

    // ---- Per-thread state ownership: 1 element each ----
    const int s_l  = tid >> 5;            // 0..7
    const int i_l  = tid & 31;            // 0..31
    const int s_gl = s0 + s_l;
    const int i_gl = row0 + i_l;
    const int e    = s_l * ROWBLK + i_l;

    const float* inp_base = inp + (size_t)s_gl * TT * ND + i_gl;
    float* out_base       = out + (size_t)s_gl * TT * ND + i_gl;
    const int hslot = s_gl * ND + hpos(i_gl);

    // Dedup prefetch: thread (tid&31)==rb covers line rb of 8 sample rows.
    const bool do_pf = ((tid & 31) == rb);
    const float* pf_base = inp + (size_t)(s0 + (tid >> 5)) * TT * ND + rb * 32;

    // ---- Production 0: h0 ----
    float hprev = h0[(size_t)s_gl * ND + i_gl];
    out_base[0] = hprev;
    g_hbuf[0][hslot] = __float2half_rn(hprev);
    __syncthreads();
    if (tid == 0) flag_release(&g_flags[sb][rb], 1u);

    // Warm prefetch for chunk 0 (rows ts=0,1).
    if (do_pf) {
        prefetch_l2(pf_base);
        prefetch_l2(pf_base + ND);
    }

    // x base for the Q GEMM (B operand rows = samples s0+g).
    const float* xq_base = inp + (size_t)(s0 + g) * TT * ND;

    // ================= Main loop: 1023 double-steps =================
    for (int s = 0; s < (TT - 2) / 2; s++) {
        const int ts = 2 * s;   // produces h[ts+1], h[ts+2] from h[ts]

        float xa = __ldcs(inp_base + (size_t)ts * ND);
        float xb = __ldcs(inp_base + (size_t)(ts + 1) * ND);

        // Split accumulators: even kt -> *a, odd kt -> *b (halves the RAW
        // dependency chain through the HMMA accumulators).
        float d1a[2][4], d1b[2][4];   // A h
        float d2a[2][4], d2b[2][4];   // A x_ts (pre) + A^2 h (post)
#pragma unroll
        for (int m = 0; m < 2; m++)
#pragma unroll
            for (int c = 0; c < 4; c++) {
                d1a[m][c] = 0.f; d1b[m][c] = 0.f;
                d2a[m][c] = 0.f; d2b[m][c] = 0.f;
            }

        // ---- Q = A x_ts : dependency-free (x prefetched last chunk) ----
#pragma unroll
        for (int kt = 0; kt < KTILES; kt++) {
            int kb = (w * KTILES + kt) * 16 + 2 * tig;
            const float* xp = xq_base + (size_t)ts * ND + kb;
            float2 v0 = __ldcs((const float2*)xp);
            float2 v1 = __ldcs((const float2*)(xp + 8));
            __half2 hq0 = __floats2half2_rn(v0.x, v0.y);
            __half2 hq1 = __floats2half2_rn(v1.x, v1.y);
            uint32_t b0 = *(uint32_t*)&hq0;
            uint32_t b1 = *(uint32_t*)&hq1;
            float* t0 = (kt & 1) ? d2b[0] : d2a[0];
            float* t1 = (kt & 1) ? d2b[1] : d2a[1];
            mma16816(t0, afrag[kt][0], b0, b1);
            mma16816(t1, afrag[kt][1], b0, b1);
        }

        // Prefetch next chunk's x rows into L2 (deduplicated across CTAs).
        if (do_pf && ts + 2 < TT) {
            prefetch_l2(pf_base + (size_t)(ts + 2) * ND);
            prefetch_l2(pf_base + (size_t)(ts + 3) * ND);
        }

        // ---- Wait: warp 0 polls all 32 producers of this group ----
        if (w == 0) {
            const volatile unsigned* f = &g_flags[sb][lane];
            unsigned v = flag_acquire(f);
            while (__ballot_sync(0xffffffffu, v < (unsigned)(s + 1))) {
                if (v < (unsigned)(s + 1)) v = flag_acquire(f);
            }
        }
        __syncthreads();

        const __half* hb = g_hbuf[s & 1];

        // ---- P1 = A h, D2 += A^2 h (split accumulator chains) ----
#pragma unroll
        for (int kt = 0; kt < KTILES; kt++) {
            int koff = (w * KTILES + kt) * 16 + tig * 4;
            uint2 b = *(const uint2*)(hb + (size_t)(s0 + g) * ND + koff);
            float* u0 = (kt & 1) ? d1b[0] : d1a[0];
            float* u1 = (kt & 1) ? d1b[1] : d1a[1];
            float* t0 = (kt & 1) ? d2b[0] : d2a[0];
            float* t1 = (kt & 1) ? d2b[1] : d2a[1];
            mma16816(u0, afrag[kt][0],  b.x, b.y);
            mma16816(u1, afrag[kt][1],  b.x, b.y);
            mma16816(t0, a2frag[kt][0], b.x, b.y);
            mma16816(t1, a2frag[kt][1], b.x, b.y);
        }

        // ---- cross-warp reduction (interleaved float2) ----
#pragma unroll
        for (int m = 0; m < 2; m++)
#pragma unroll
            for (int c = 0; c < 4; c++) {
                int i_loc = m * 16 + g + ((c >> 1) << 3);
                int s_loc = tig * 2 + (c & 1);
                psum[w][s_loc * ROWBLK + i_loc] =
                    make_float2(d1a[m][c] + d1b[m][c],
                                d2a[m][c] + d2b[m][c]);
            }
        __syncthreads();

        float P1 = 0.f, D2 = 0.f;
#pragma unroll
        for (int ww = 0; ww < NWARPS; ww++) {
            float2 p = psum[ww][e];
            P1 += p.x; D2 += p.y;
        }

        float h1 = BETA * hprev + ALPHA * (P1 + xa);
        float h2 = BETA * h1 + ABC * P1 + A2C * D2 + ALPHA * xb;
        hprev = h2;

        // Publish state; split barrier: warps 1-7 arrive and flow on to the
        // outputs + next chunk's Q, warp 0 syncs (acquiring all hbuf stores)
        // and issues the gpu-scope release.
        g_hbuf[(s + 1) & 1][hslot] = __float2half_rn(h2);
        if (w == 0) {
            asm volatile("bar.sync 1, %0;" :: "n"(NTHREADS) : "memory");
            if (tid == 0) flag_release(&g_flags[sb][rb], (unsigned)(s + 2));
        } else {
            asm volatile("bar.arrive 1, %0;" :: "n"(NTHREADS) : "memory");
        }

        __stcs(out_base + (size_t)(ts + 1) * ND, h1);
        __stcs(out_base + (size_t)(ts + 2) * ND, h2);
    }

    // ================= Epilogue: final single step t = TT-1 =================
    {
        const int s  = (TT - 2) / 2;   // 1023
        const int ts = 2 * s;          // 2046
        float xa = __ldcs(inp_base + (size_t)ts * ND);

        if (w == 0) {
            const volatile unsigned* f = &g_flags[sb][lane];
            unsigned v = flag_acquire(f);
            while (__ballot_sync(0xffffffffu, v < (unsigned)(s + 1))) {
                if (v < (unsigned)(s + 1)) v = flag_acquire(f);
            }
        }
        __syncthreads();

        const __half* hb = g_hbuf[s & 1];
        float d1a[2][4], d1b[2][4];
#pragma unroll
        for (int m = 0; m < 2; m++)
#pragma unroll
            for (int c = 0; c < 4; c++) { d1a[m][c] = 0.f; d1b[m][c] = 0.f; }

#pragma unroll
        for (int kt = 0; kt < KTILES; kt++) {
            int koff = (w * KTILES + kt) * 16 + tig * 4;
            uint2 b = *(const uint2*)(hb + (size_t)(s0 + g) * ND + koff);
            float* u0 = (kt & 1) ? d1b[0] : d1a[0];
            float* u1 = (kt & 1) ? d1b[1] : d1a[1];
            mma16816(u0, afrag[kt][0], b.x, b.y);
            mma16816(u1, afrag[kt][1], b.x, b.y);
        }
#pragma unroll
        for (int m = 0; m < 2; m++)
#pragma unroll
            for (int c = 0; c < 4; c++) {
                int i_loc = m * 16 + g + ((c >> 1) << 3);
                int s_loc = tig * 2 + (c & 1);
                psum[w][s_loc * ROWBLK + i_loc].x = d1a[m][c] + d1b[m][c];
            }
        __syncthreads();

        float P1 = 0.f;
#pragma unroll
        for (int ww = 0; ww < NWARPS; ww++) P1 += psum[ww][e].x;

        float h1 = BETA * hprev + ALPHA * (P1 + xa);
        __stcs(out_base + (size_t)(ts + 1) * ND, h1);
    }

    // ---- Cleanup so graph replays start from flags == 0 ----
    grid_barrier();
    if (tid == 0) g_flags[sb][rb] = 0u;
}

extern "C" void kernel_launch(void* const* d_in, const int* in_sizes, int n_in,
                              void* d_out, int out_size) {
    const float* inp = (const float*)d_in[0];
    const float* A   = (const float*)d_in[1];
    const float* h0  = (const float*)d_in[2];
    float* out       = (float*)d_out;
    rnn_kernel<<<GRID, NTHREADS>>>(inp, A, h0, out);
}